// round 16
// baseline (speedup 1.0000x reference)
#include <cuda_runtime.h>
#include <cuda_fp16.h>
#include <cstdint>
#include <math.h>

#define Bc 2
#define Tc 2048
#define Sc 2048
#define Ec 1024
#define Hc 16
#define HDc 64
#define QSCALE 0.125f

// Scratch (__device__ globals; allocation-free)
__device__ __half g_q[(size_t)Bc*Hc*Tc*HDc];  // [bh,t,d] fp16
__device__ __half g_k[(size_t)Bc*Hc*Sc*HDc];  // [bh,s,d] fp16
__device__ __half g_v[(size_t)Bc*Hc*Sc*HDc];  // [bh,s,d] fp16
__device__ float  g_o[(size_t)Bc*Tc*Ec];      // [b,t,h,d]  attn out pre-Wo
__device__ float  g_c[Bc*Hc*Tc];              // m + log(sum)

__device__ __forceinline__ uint32_t smem_u32(const void* p) {
    uint32_t a;
    asm("{ .reg .u64 t; cvta.to.shared.u64 t, %1; cvt.u32.u64 %0, t; }" : "=r"(a) : "l"(p));
    return a;
}
__device__ __forceinline__ void mma_f16(float c[4], const uint32_t a[4], uint32_t b0, uint32_t b1) {
    asm volatile(
        "mma.sync.aligned.m16n8k16.row.col.f32.f16.f16.f32 "
        "{%0,%1,%2,%3}, {%4,%5,%6,%7}, {%8,%9}, {%0,%1,%2,%3};"
        : "+f"(c[0]), "+f"(c[1]), "+f"(c[2]), "+f"(c[3])
        : "r"(a[0]), "r"(a[1]), "r"(a[2]), "r"(a[3]), "r"(b0), "r"(b1));
}
__device__ __forceinline__ void ldsm4(uint32_t r[4], uint32_t addr) {
    asm volatile("ldmatrix.sync.aligned.m8n8.x4.shared.b16 {%0,%1,%2,%3}, [%4];"
        : "=r"(r[0]), "=r"(r[1]), "=r"(r[2]), "=r"(r[3]) : "r"(addr));
}
__device__ __forceinline__ void ldsm4t(uint32_t r[4], uint32_t addr) {
    asm volatile("ldmatrix.sync.aligned.m8n8.x4.trans.shared.b16 {%0,%1,%2,%3}, [%4];"
        : "=r"(r[0]), "=r"(r[1]), "=r"(r[2]), "=r"(r[3]) : "r"(addr));
}
__device__ __forceinline__ uint32_t pack_f16(float lo, float hi) {
    uint32_t r; asm("cvt.rn.f16x2.f32 %0, %1, %2;" : "=r"(r) : "f"(hi), "f"(lo)); return r;
}
__device__ __forceinline__ void cp16(uint32_t smem_addr, const void* gptr) {
    asm volatile("cp.async.cg.shared.global [%0], [%1], 16;"
        :: "r"(smem_addr), "l"(gptr) : "memory");
}
#define CP_COMMIT() asm volatile("cp.async.commit_group;" ::: "memory")
#define CP_WAIT0()  asm volatile("cp.async.wait_group 0;" ::: "memory")

// ---------------------------------------------------------------------------
// Double-buffered fp16 GEMM (fp32 in, fp16 operands, fp32 accum):
//   C = A[M,1024] @ W[1024,1024]^T (+bias)
// MODE 0: batched QKV projection (blockIdx.z selects q/k/v) -> fp16 g_q/g_k/g_v
// MODE 3: output projection (flat fp32 [row, col] out)
// ---------------------------------------------------------------------------
template<int MODE>
__global__ void __launch_bounds__(256, 2) gemm_db(
    const float* __restrict__ A0, const float* __restrict__ A1, const float* __restrict__ A2,
    const float* __restrict__ W0, const float* __restrict__ W1, const float* __restrict__ W2,
    const float* __restrict__ bias0, const float* __restrict__ bias1, const float* __restrict__ bias2,
    float* __restrict__ Cout)
{
    extern __shared__ uint32_t ds[];
    uint32_t* const Abuf[2] = { ds,        ds + 5120 };
    uint32_t* const Bbuf[2] = { ds + 2560, ds + 7680 };

    const int tid  = threadIdx.x;
    const int wid  = tid >> 5;
    const int lane = tid & 31;
    const int wrow = wid >> 2;
    const int wcol = wid & 3;
    const int bm = blockIdx.y * 128;
    const int bn = blockIdx.x * 128;
    const int z  = blockIdx.z;

    const float* A; const float* W; const float* bias; float scale;
    __half* hdst = nullptr;
    if (MODE == 0) {
        A    = (z == 0) ? A0 : (z == 1) ? A1 : A2;
        W    = (z == 0) ? W0 : (z == 1) ? W1 : W2;
        bias = (z == 0) ? bias0 : (z == 1) ? bias1 : bias2;
        scale = (z == 0) ? QSCALE : 1.0f;
        hdst = (z == 0) ? g_q : (z == 1) ? g_k : g_v;
    } else {
        A = A0; W = W0; bias = bias0; scale = 1.0f;
    }

    float c[4][4][4];
    #pragma unroll
    for (int i = 0; i < 4; i++)
        #pragma unroll
        for (int j = 0; j < 4; j++)
            #pragma unroll
            for (int u = 0; u < 4; u++) c[i][j][u] = 0.f;

    const int fRow  = (lane & 7) + ((lane >> 3) & 1) * 8;
    const int fColH = (lane >> 4) * 8;
    const uint32_t sA[2] = { smem_u32(Abuf[0]), smem_u32(Abuf[1]) };
    const uint32_t sB[2] = { smem_u32(Bbuf[0]), smem_u32(Bbuf[1]) };

    const int lrw = tid >> 3;
    const int lc4 = (tid & 7) * 4;

    float4 ra[4], rb[4];
    #pragma unroll
    for (int i = 0; i < 4; i++) {
        int row = lrw + i * 32;
        ra[i] = *(const float4*)(A + (size_t)(bm + row) * Ec + lc4);
        rb[i] = *(const float4*)(W + (size_t)(bn + row) * Ec + lc4);
    }
    #pragma unroll
    for (int i = 0; i < 4; i++) {
        int row = lrw + i * 32;
        int idx = row * 20 + (lc4 >> 1);
        *(uint2*)&Abuf[0][idx] = make_uint2(pack_f16(ra[i].x, ra[i].y), pack_f16(ra[i].z, ra[i].w));
        *(uint2*)&Bbuf[0][idx] = make_uint2(pack_f16(rb[i].x, rb[i].y), pack_f16(rb[i].z, rb[i].w));
    }
    __syncthreads();

    for (int ks = 0; ks < 32; ks++) {
        const int cur = ks & 1;
        if (ks < 31) {
            #pragma unroll
            for (int i = 0; i < 4; i++) {
                int row = lrw + i * 32;
                ra[i] = *(const float4*)(A + (size_t)(bm + row) * Ec + (ks + 1) * 32 + lc4);
                rb[i] = *(const float4*)(W + (size_t)(bn + row) * Ec + (ks + 1) * 32 + lc4);
            }
        }
        #pragma unroll
        for (int k16 = 0; k16 < 2; k16++) {
            uint32_t af[4][4], bf[4][2];
            #pragma unroll
            for (int mt = 0; mt < 4; mt++)
                ldsm4(af[mt], sA[cur] + (uint32_t)(((wrow * 64 + mt * 16 + fRow) * 40
                                                    + k16 * 16 + fColH) * 2));
            #pragma unroll
            for (int np = 0; np < 2; np++) {
                uint32_t t4[4];
                ldsm4(t4, sB[cur] + (uint32_t)(((wcol * 32 + np * 16 + fRow) * 40
                                                + k16 * 16 + fColH) * 2));
                bf[2*np][0] = t4[0]; bf[2*np][1] = t4[2];
                bf[2*np+1][0] = t4[1]; bf[2*np+1][1] = t4[3];
            }
            #pragma unroll
            for (int mt = 0; mt < 4; mt++)
                #pragma unroll
                for (int nt = 0; nt < 4; nt++)
                    mma_f16(c[mt][nt], af[mt], bf[nt][0], bf[nt][1]);
        }
        if (ks < 31) {
            #pragma unroll
            for (int i = 0; i < 4; i++) {
                int row = lrw + i * 32;
                int idx = row * 20 + (lc4 >> 1);
                *(uint2*)&Abuf[cur ^ 1][idx] = make_uint2(pack_f16(ra[i].x, ra[i].y),
                                                          pack_f16(ra[i].z, ra[i].w));
                *(uint2*)&Bbuf[cur ^ 1][idx] = make_uint2(pack_f16(rb[i].x, rb[i].y),
                                                          pack_f16(rb[i].z, rb[i].w));
            }
        }
        __syncthreads();
    }

    const int lrow = lane >> 2;
    const int lk   = lane & 3;
    #pragma unroll
    for (int mt = 0; mt < 4; mt++) {
        #pragma unroll
        for (int half = 0; half < 2; half++) {
            int row = bm + wrow * 64 + mt * 16 + lrow + half * 8;
            #pragma unroll
            for (int nt = 0; nt < 4; nt++) {
                int col = bn + wcol * 32 + nt * 8 + lk * 2;
                float v0 = c[mt][nt][half * 2];
                float v1 = c[mt][nt][half * 2 + 1];
                if (MODE == 0) {
                    int b = row >> 11, t = row & 2047;
                    int h = col >> 6, d = col & 63;
                    *(uint32_t*)&hdst[(((size_t)(b * Hc + h)) * Tc + t) * HDc + d] =
                        pack_f16((v0 + bias[col]) * scale, (v1 + bias[col + 1]) * scale);
                } else {
                    *(float2*)&Cout[(size_t)row * Ec + col] =
                        make_float2(v0 + bias[col], v1 + bias[col + 1]);
                }
            }
        }
    }
}

// ---------------------------------------------------------------------------
// attn_fused (all-fp16, cp.async double-buffered K/V): per (bh, 64-row t-tile).
// One __syncthreads per s-iter; tile i+1 copies (gmem->smem, no registers)
// overlap compute of tile i.  Writes g_o = O/sum and g_c = m + log(sum).
// ---------------------------------------------------------------------------
__global__ void __launch_bounds__(128, 4) attn_fused(
    const unsigned char* __restrict__ am, const unsigned char* __restrict__ kpm)
{
    __shared__ uint32_t Ks2[2 * 2304];   // 2 x (64 rows x 72-half stride)
    __shared__ uint32_t Vs2[2 * 2304];

    const int tid  = threadIdx.x;
    const int w    = tid >> 5;
    const int lane = tid & 31;
    const int lrow = lane >> 2;
    const int lk   = lane & 3;
    const int tbase = blockIdx.x * 64;
    const int bh = blockIdx.y;
    const int b = bh >> 4, h = bh & 15;

    const __half* Q  = g_q + (size_t)bh * Tc * HDc;
    const __half* Kg = g_k + (size_t)bh * Sc * HDc;
    const __half* Vg = g_v + (size_t)bh * Sc * HDc;

    const uint32_t sK = smem_u32(Ks2);
    const uint32_t sV = smem_u32(Vs2);

    const int fRow  = (lane & 7) + ((lane >> 3) & 1) * 8;
    const int fColH = (lane >> 4) * 8;

    const int ldRow = tid >> 3;           // 0..15 (x4 chunks of 16 rows)
    const int ldC8  = (tid & 7) * 8;      // halves

    // stage Q -> Ks2 buf1 (regular stores); cp.async K0/V0 -> buf0
    #pragma unroll
    for (int i = 0; i < 4; i++) {
        int row = ldRow + i * 16;
        *(uint4*)((char*)Ks2 + 9216 + row * 144 + ldC8 * 2) =
            *(const uint4*)(Q + (size_t)(tbase + row) * HDc + ldC8);
        cp16(sK + (uint32_t)(row * 144 + ldC8 * 2), Kg + (size_t)row * HDc + ldC8);
        cp16(sV + (uint32_t)(row * 144 + ldC8 * 2), Vg + (size_t)row * HDc + ldC8);
    }
    CP_COMMIT();
    __syncthreads();
    uint32_t aQ[4][4];
    #pragma unroll
    for (int ks = 0; ks < 4; ks++)
        ldsm4(aQ[ks], sK + 9216u + (uint32_t)((w * 16 + fRow) * 144 + (ks * 16 + fColH) * 2));

    float Oa[8][4];
    #pragma unroll
    for (int i = 0; i < 8; i++)
        #pragma unroll
        for (int u = 0; u < 4; u++) Oa[i][u] = 0.f;
    float m_lo = -1e30f, m_hi = -1e30f, s_lo = 0.f, s_hi = 0.f;

    const int t_lo = tbase + w * 16 + lrow;
    const int t_hi = t_lo + 8;

    for (int it = 0; it < 32; it++) {
        const uint32_t base = (it & 1) ? 9216u : 0u;
        const uint32_t nbase = base ^ 9216u;

        // tile `it` is complete; barrier also ensures compute(it-1) done in all
        // warps (and, at it=0, that every warp has read its Q fragments)
        CP_WAIT0();
        __syncthreads();

        // kick off copy of tile it+1 into the other buffer (no registers)
        if (it < 31) {
            #pragma unroll
            for (int i = 0; i < 4; i++) {
                int row = ldRow + i * 16;
                int grow = (it + 1) * 64 + row;
                cp16(sK + nbase + (uint32_t)(row * 144 + ldC8 * 2),
                     Kg + (size_t)grow * HDc + ldC8);
                cp16(sV + nbase + (uint32_t)(row * 144 + ldC8 * 2),
                     Vg + (size_t)grow * HDc + ldC8);
            }
            CP_COMMIT();
        }

        // ---- S = Q @ K^T ----
        float S[8][4];
        #pragma unroll
        for (int nt = 0; nt < 8; nt++)
            #pragma unroll
            for (int u = 0; u < 4; u++) S[nt][u] = 0.f;
        #pragma unroll
        for (int ks = 0; ks < 4; ks++) {
            #pragma unroll
            for (int np = 0; np < 4; np++) {
                uint32_t t4[4];
                ldsm4(t4, sK + base + (uint32_t)((np * 16 + fRow) * 144 + (ks * 16 + fColH) * 2));
                mma_f16(S[2*np],     aQ[ks], t4[0], t4[2]);
                mma_f16(S[2*np + 1], aQ[ks], t4[1], t4[3]);
            }
        }

        const int s0 = it * 64;
        float tmax_lo = -1e30f, tmax_hi = -1e30f;
        #pragma unroll
        for (int nt = 0; nt < 8; nt++) {
            int col = s0 + nt * 8 + lk * 2;
            uchar2 a0 = *(const uchar2*)&am[(size_t)t_lo * Sc + col];
            uchar2 a1 = *(const uchar2*)&am[(size_t)t_hi * Sc + col];
            uchar2 kp = *(const uchar2*)&kpm[(size_t)b * Sc + col];
            if (a0.x | kp.x) S[nt][0] = 1e-10f;
            if (a0.y | kp.y) S[nt][1] = 1e-10f;
            if (a1.x | kp.x) S[nt][2] = 1e-10f;
            if (a1.y | kp.y) S[nt][3] = 1e-10f;
            tmax_lo = fmaxf(tmax_lo, fmaxf(S[nt][0], S[nt][1]));
            tmax_hi = fmaxf(tmax_hi, fmaxf(S[nt][2], S[nt][3]));
        }
        tmax_lo = fmaxf(tmax_lo, __shfl_xor_sync(0xffffffffu, tmax_lo, 1));
        tmax_lo = fmaxf(tmax_lo, __shfl_xor_sync(0xffffffffu, tmax_lo, 2));
        tmax_hi = fmaxf(tmax_hi, __shfl_xor_sync(0xffffffffu, tmax_hi, 1));
        tmax_hi = fmaxf(tmax_hi, __shfl_xor_sync(0xffffffffu, tmax_hi, 2));

        float mnew_lo = fmaxf(m_lo, tmax_lo);
        float mnew_hi = fmaxf(m_hi, tmax_hi);
        float f_lo = __expf(m_lo - mnew_lo);
        float f_hi = __expf(m_hi - mnew_hi);
        m_lo = mnew_lo; m_hi = mnew_hi;
        s_lo *= f_lo;   s_hi *= f_hi;
        #pragma unroll
        for (int nd = 0; nd < 8; nd++) {
            Oa[nd][0] *= f_lo; Oa[nd][1] *= f_lo;
            Oa[nd][2] *= f_hi; Oa[nd][3] *= f_hi;
        }

        uint32_t aP[4][4];
        #pragma unroll
        for (int nt = 0; nt < 8; nt++) {
            float p0 = __expf(S[nt][0] - m_lo);
            float p1 = __expf(S[nt][1] - m_lo);
            float p2 = __expf(S[nt][2] - m_hi);
            float p3 = __expf(S[nt][3] - m_hi);
            s_lo += p0 + p1;
            s_hi += p2 + p3;
            int kk = nt >> 1, hi = (nt & 1) * 2;
            aP[kk][hi]     = pack_f16(p0, p1);
            aP[kk][hi + 1] = pack_f16(p2, p3);
        }

        #pragma unroll
        for (int kk = 0; kk < 4; kk++) {
            int vrow = kk * 16 + fRow;
            #pragma unroll
            for (int nd16 = 0; nd16 < 4; nd16++) {
                uint32_t t4[4];
                int vcol = nd16 * 16 + (lane >> 4) * 8;
                ldsm4t(t4, sV + base + (uint32_t)(vrow * 144 + vcol * 2));
                mma_f16(Oa[nd16 * 2],     aP[kk], t4[0], t4[1]);
                mma_f16(Oa[nd16 * 2 + 1], aP[kk], t4[2], t4[3]);
            }
        }
    }

    float r_lo = s_lo, r_hi = s_hi;
    r_lo += __shfl_xor_sync(0xffffffffu, r_lo, 1);
    r_lo += __shfl_xor_sync(0xffffffffu, r_lo, 2);
    r_hi += __shfl_xor_sync(0xffffffffu, r_hi, 1);
    r_hi += __shfl_xor_sync(0xffffffffu, r_hi, 2);
    const float inv_lo = 1.0f / r_lo;
    const float inv_hi = 1.0f / r_hi;

    #pragma unroll
    for (int nd = 0; nd < 8; nd++) {
        int d = nd * 8 + lk * 2;
        *(float2*)&g_o[(((size_t)b * Tc + t_lo) * Hc + h) * HDc + d] =
            make_float2(Oa[nd][0] * inv_lo, Oa[nd][1] * inv_lo);
        *(float2*)&g_o[(((size_t)b * Tc + t_hi) * Hc + h) * HDc + d] =
            make_float2(Oa[nd][2] * inv_hi, Oa[nd][3] * inv_hi);
    }
    if (lk == 0) {
        g_c[(size_t)bh * Tc + t_lo] = m_lo + __logf(r_lo);
        g_c[(size_t)bh * Tc + t_hi] = m_hi + __logf(r_hi);
    }
}

// ---------------------------------------------------------------------------
// headmax_gemm (cp.async double-buffered over h): per (b, 64x64 t x s tile).
// Recomputes S_h (bit-identical fp16 mma) for all 16 heads;
//   attn_max[b,t,s] = exp(max_h (S_h - c[b,h,t])).
// ---------------------------------------------------------------------------
__global__ void __launch_bounds__(128, 4) headmax_gemm(
    const unsigned char* __restrict__ am, const unsigned char* __restrict__ kpm,
    float* __restrict__ out2)
{
    __shared__ uint32_t Qs2[2 * 2304];
    __shared__ uint32_t Ks2[2 * 2304];

    const int tid  = threadIdx.x;
    const int w    = tid >> 5;
    const int lane = tid & 31;
    const int lrow = lane >> 2;
    const int lk   = lane & 3;
    const int b  = blockIdx.z;
    const int tb = blockIdx.y * 64;
    const int sb = blockIdx.x * 64;

    const uint32_t sQ = smem_u32(Qs2);
    const uint32_t sKb = smem_u32(Ks2);

    const int fRow  = (lane & 7) + ((lane >> 3) & 1) * 8;
    const int fColH = (lane >> 4) * 8;

    const int ldRow = tid >> 3;
    const int ldC8  = (tid & 7) * 8;

    const int t_lo = tb + w * 16 + lrow;
    const int t_hi = t_lo + 8;

    // preload h = 0 via cp.async into buf0
    {
        const __half* Q0 = g_q + (size_t)(b * Hc) * Tc * HDc;
        const __half* K0 = g_k + (size_t)(b * Hc) * Sc * HDc;
        #pragma unroll
        for (int i = 0; i < 4; i++) {
            int row = ldRow + i * 16;
            cp16(sQ + (uint32_t)(row * 144 + ldC8 * 2), Q0 + (size_t)(tb + row) * HDc + ldC8);
            cp16(sKb + (uint32_t)(row * 144 + ldC8 * 2), K0 + (size_t)(sb + row) * HDc + ldC8);
        }
        CP_COMMIT();
    }

    // precompute per-thread mask bits (overlaps with h=0 copy)
    uint32_t mbits = 0;
    #pragma unroll
    for (int nt = 0; nt < 8; nt++) {
        int col = sb + nt * 8 + lk * 2;
        uchar2 a0 = *(const uchar2*)&am[(size_t)t_lo * Sc + col];
        uchar2 a1 = *(const uchar2*)&am[(size_t)t_hi * Sc + col];
        uchar2 kp = *(const uchar2*)&kpm[(size_t)b * Sc + col];
        if (a0.x | kp.x) mbits |= 1u << (nt * 4 + 0);
        if (a0.y | kp.y) mbits |= 1u << (nt * 4 + 1);
        if (a1.x | kp.x) mbits |= 1u << (nt * 4 + 2);
        if (a1.y | kp.y) mbits |= 1u << (nt * 4 + 3);
    }

    float best[8][4];
    #pragma unroll
    for (int nt = 0; nt < 8; nt++)
        #pragma unroll
        for (int u = 0; u < 4; u++) best[nt][u] = -1e30f;

    for (int h = 0; h < Hc; h++) {
        const uint32_t base = (h & 1) ? 9216u : 0u;
        const uint32_t nbase = base ^ 9216u;
        const int bh = b * Hc + h;

        CP_WAIT0();
        __syncthreads();

        // kick off next head's copies (no registers)
        if (h < Hc - 1) {
            const __half* Qn = g_q + (size_t)(bh + 1) * Tc * HDc;
            const __half* Kn = g_k + (size_t)(bh + 1) * Sc * HDc;
            #pragma unroll
            for (int i = 0; i < 4; i++) {
                int row = ldRow + i * 16;
                cp16(sQ + nbase + (uint32_t)(row * 144 + ldC8 * 2),
                     Qn + (size_t)(tb + row) * HDc + ldC8);
                cp16(sKb + nbase + (uint32_t)(row * 144 + ldC8 * 2),
                     Kn + (size_t)(sb + row) * HDc + ldC8);
            }
            CP_COMMIT();
        }

        uint32_t aQ[4][4];
        #pragma unroll
        for (int ks = 0; ks < 4; ks++)
            ldsm4(aQ[ks], sQ + base + (uint32_t)((w * 16 + fRow) * 144 + (ks * 16 + fColH) * 2));

        float S[8][4];
        #pragma unroll
        for (int nt = 0; nt < 8; nt++)
            #pragma unroll
            for (int u = 0; u < 4; u++) S[nt][u] = 0.f;
        #pragma unroll
        for (int ks = 0; ks < 4; ks++) {
            #pragma unroll
            for (int np = 0; np < 4; np++) {
                uint32_t t4[4];
                ldsm4(t4, sKb + base + (uint32_t)((np * 16 + fRow) * 144 + (ks * 16 + fColH) * 2));
                mma_f16(S[2*np],     aQ[ks], t4[0], t4[2]);
                mma_f16(S[2*np + 1], aQ[ks], t4[1], t4[3]);
            }
        }

        const float c_lo = g_c[(size_t)bh * Tc + t_lo];
        const float c_hi = g_c[(size_t)bh * Tc + t_hi];
        #pragma unroll
        for (int nt = 0; nt < 8; nt++) {
            float v0 = (mbits >> (nt * 4 + 0)) & 1 ? 1e-10f : S[nt][0];
            float v1 = (mbits >> (nt * 4 + 1)) & 1 ? 1e-10f : S[nt][1];
            float v2 = (mbits >> (nt * 4 + 2)) & 1 ? 1e-10f : S[nt][2];
            float v3 = (mbits >> (nt * 4 + 3)) & 1 ? 1e-10f : S[nt][3];
            best[nt][0] = fmaxf(best[nt][0], v0 - c_lo);
            best[nt][1] = fmaxf(best[nt][1], v1 - c_lo);
            best[nt][2] = fmaxf(best[nt][2], v2 - c_hi);
            best[nt][3] = fmaxf(best[nt][3], v3 - c_hi);
        }
    }

    #pragma unroll
    for (int nt = 0; nt < 8; nt++) {
        int col = sb + nt * 8 + lk * 2;
        *(float2*)&out2[((size_t)b * Tc + t_lo) * Sc + col] =
            make_float2(__expf(best[nt][0]), __expf(best[nt][1]));
        *(float2*)&out2[((size_t)b * Tc + t_hi) * Sc + col] =
            make_float2(__expf(best[nt][2]), __expf(best[nt][3]));
    }
}

// ---------------------------------------------------------------------------
extern "C" void kernel_launch(void* const* d_in, const int* in_sizes, int n_in,
                              void* d_out, int out_size)
{
    const float* query = (const float*)d_in[0];
    const float* key   = (const float*)d_in[1];
    const float* value = (const float*)d_in[2];
    const unsigned char* kpm = (const unsigned char*)d_in[3];
    const unsigned char* am  = (const unsigned char*)d_in[4];
    const float* Wq = (const float*)d_in[5];
    const float* bq = (const float*)d_in[6];
    const float* Wk = (const float*)d_in[7];
    const float* bk = (const float*)d_in[8];
    const float* Wv = (const float*)d_in[9];
    const float* bv = (const float*)d_in[10];
    const float* Wo = (const float*)d_in[11];
    const float* bo = (const float*)d_in[12];

    float* out      = (float*)d_out;
    float* attn_max = (float*)d_out + (size_t)Bc * Tc * Ec;

    float *po;
    cudaGetSymbolAddress((void**)&po, g_o);

    static cudaStream_t s2 = nullptr;
    static cudaEvent_t evFork = nullptr, evJoin = nullptr;
    if (s2 == nullptr) {
        cudaStreamCreateWithFlags(&s2, cudaStreamNonBlocking);
        cudaEventCreateWithFlags(&evFork, cudaEventDisableTiming);
        cudaEventCreateWithFlags(&evJoin, cudaEventDisableTiming);
    }

    const int GEMM_SMEM = 4 * 2560 * 4;   // 40960 B (fp16 double buffer)
    cudaFuncSetAttribute(gemm_db<0>, cudaFuncAttributeMaxDynamicSharedMemorySize, GEMM_SMEM);
    cudaFuncSetAttribute(gemm_db<3>, cudaFuncAttributeMaxDynamicSharedMemorySize, GEMM_SMEM);

    dim3 thr(256);

    // Batched Q/K/V projections -> fp16 (grid.z = 0,1,2)
    gemm_db<0><<<dim3(Ec / 128, (Bc * Tc) / 128, 3), thr, GEMM_SMEM>>>(
        query, key, value, Wq, Wk, Wv, bq, bk, bv, nullptr);

    // Fused score + online softmax + P@V  (writes g_o, g_c only)
    attn_fused<<<dim3(Tc / 64, Bc * Hc), dim3(128)>>>(am, kpm);

    // fork: attn_max recompute on side stream, out-projection on main stream
    cudaEventRecord(evFork, 0);
    cudaStreamWaitEvent(s2, evFork, 0);

    headmax_gemm<<<dim3(Sc / 64, Tc / 64, Bc), dim3(128), 0, s2>>>(am, kpm, attn_max);

    gemm_db<3><<<dim3(Ec / 128, (Bc * Tc) / 128, 1), thr, GEMM_SMEM>>>(
        po, nullptr, nullptr, Wo, nullptr, nullptr, bo, nullptr, nullptr, out);

    cudaEventRecord(evJoin, s2);
    cudaStreamWaitEvent(0, evJoin, 0);
}

// round 17
// speedup vs baseline: 1.3976x; 1.3976x over previous
#include <cuda_runtime.h>
#include <cuda_fp16.h>
#include <cstdint>
#include <math.h>

#define Bc 2
#define Tc 2048
#define Sc 2048
#define Ec 1024
#define Hc 16
#define HDc 64
#define QSCALE 0.125f

// Scratch (__device__ globals; allocation-free)
__device__ __half g_q[(size_t)Bc*Hc*Tc*HDc];  // [bh,t,d] fp16
__device__ __half g_k[(size_t)Bc*Hc*Sc*HDc];  // [bh,s,d] fp16
__device__ __half g_v[(size_t)Bc*Hc*Sc*HDc];  // [bh,s,d] fp16
__device__ float  g_o[(size_t)Bc*Tc*Ec];      // [b,t,h,d]  attn out pre-Wo
__device__ float  g_c[Bc*Hc*Tc];              // m + log(sum)

__device__ __forceinline__ uint32_t smem_u32(const void* p) {
    uint32_t a;
    asm("{ .reg .u64 t; cvta.to.shared.u64 t, %1; cvt.u32.u64 %0, t; }" : "=r"(a) : "l"(p));
    return a;
}
__device__ __forceinline__ void mma_f16(float c[4], const uint32_t a[4], uint32_t b0, uint32_t b1) {
    asm volatile(
        "mma.sync.aligned.m16n8k16.row.col.f32.f16.f16.f32 "
        "{%0,%1,%2,%3}, {%4,%5,%6,%7}, {%8,%9}, {%0,%1,%2,%3};"
        : "+f"(c[0]), "+f"(c[1]), "+f"(c[2]), "+f"(c[3])
        : "r"(a[0]), "r"(a[1]), "r"(a[2]), "r"(a[3]), "r"(b0), "r"(b1));
}
__device__ __forceinline__ void ldsm4(uint32_t r[4], uint32_t addr) {
    asm volatile("ldmatrix.sync.aligned.m8n8.x4.shared.b16 {%0,%1,%2,%3}, [%4];"
        : "=r"(r[0]), "=r"(r[1]), "=r"(r[2]), "=r"(r[3]) : "r"(addr));
}
__device__ __forceinline__ void ldsm4t(uint32_t r[4], uint32_t addr) {
    asm volatile("ldmatrix.sync.aligned.m8n8.x4.trans.shared.b16 {%0,%1,%2,%3}, [%4];"
        : "=r"(r[0]), "=r"(r[1]), "=r"(r[2]), "=r"(r[3]) : "r"(addr));
}
__device__ __forceinline__ uint32_t pack_f16(float lo, float hi) {
    uint32_t r; asm("cvt.rn.f16x2.f32 %0, %1, %2;" : "=r"(r) : "f"(hi), "f"(lo)); return r;
}

// ---------------------------------------------------------------------------
// Double-buffered fp16 GEMM (fp32 in, fp16 operands, fp32 accum):
//   C = A[M,1024] @ W[1024,1024]^T (+bias)
// MODE 0: batched QKV projection (blockIdx.z selects q/k/v) -> fp16 g_q/g_k/g_v
// MODE 3: output projection (flat fp32 [row, col] out)
// ---------------------------------------------------------------------------
template<int MODE>
__global__ void __launch_bounds__(256, 2) gemm_db(
    const float* __restrict__ A0, const float* __restrict__ A1, const float* __restrict__ A2,
    const float* __restrict__ W0, const float* __restrict__ W1, const float* __restrict__ W2,
    const float* __restrict__ bias0, const float* __restrict__ bias1, const float* __restrict__ bias2,
    float* __restrict__ Cout)
{
    extern __shared__ uint32_t ds[];
    uint32_t* const Abuf[2] = { ds,        ds + 5120 };
    uint32_t* const Bbuf[2] = { ds + 2560, ds + 7680 };

    const int tid  = threadIdx.x;
    const int wid  = tid >> 5;
    const int lane = tid & 31;
    const int wrow = wid >> 2;
    const int wcol = wid & 3;
    const int bm = blockIdx.y * 128;
    const int bn = blockIdx.x * 128;
    const int z  = blockIdx.z;

    const float* A; const float* W; const float* bias; float scale;
    __half* hdst = nullptr;
    if (MODE == 0) {
        A    = (z == 0) ? A0 : (z == 1) ? A1 : A2;
        W    = (z == 0) ? W0 : (z == 1) ? W1 : W2;
        bias = (z == 0) ? bias0 : (z == 1) ? bias1 : bias2;
        scale = (z == 0) ? QSCALE : 1.0f;
        hdst = (z == 0) ? g_q : (z == 1) ? g_k : g_v;
    } else {
        A = A0; W = W0; bias = bias0; scale = 1.0f;
    }

    float c[4][4][4];
    #pragma unroll
    for (int i = 0; i < 4; i++)
        #pragma unroll
        for (int j = 0; j < 4; j++)
            #pragma unroll
            for (int u = 0; u < 4; u++) c[i][j][u] = 0.f;

    const int fRow  = (lane & 7) + ((lane >> 3) & 1) * 8;
    const int fColH = (lane >> 4) * 8;
    const uint32_t sA[2] = { smem_u32(Abuf[0]), smem_u32(Abuf[1]) };
    const uint32_t sB[2] = { smem_u32(Bbuf[0]), smem_u32(Bbuf[1]) };

    const int lrw = tid >> 3;
    const int lc4 = (tid & 7) * 4;

    float4 ra[4], rb[4];
    #pragma unroll
    for (int i = 0; i < 4; i++) {
        int row = lrw + i * 32;
        ra[i] = *(const float4*)(A + (size_t)(bm + row) * Ec + lc4);
        rb[i] = *(const float4*)(W + (size_t)(bn + row) * Ec + lc4);
    }
    #pragma unroll
    for (int i = 0; i < 4; i++) {
        int row = lrw + i * 32;
        int idx = row * 20 + (lc4 >> 1);
        *(uint2*)&Abuf[0][idx] = make_uint2(pack_f16(ra[i].x, ra[i].y), pack_f16(ra[i].z, ra[i].w));
        *(uint2*)&Bbuf[0][idx] = make_uint2(pack_f16(rb[i].x, rb[i].y), pack_f16(rb[i].z, rb[i].w));
    }
    __syncthreads();

    for (int ks = 0; ks < 32; ks++) {
        const int cur = ks & 1;
        if (ks < 31) {
            #pragma unroll
            for (int i = 0; i < 4; i++) {
                int row = lrw + i * 32;
                ra[i] = *(const float4*)(A + (size_t)(bm + row) * Ec + (ks + 1) * 32 + lc4);
                rb[i] = *(const float4*)(W + (size_t)(bn + row) * Ec + (ks + 1) * 32 + lc4);
            }
        }
        #pragma unroll
        for (int k16 = 0; k16 < 2; k16++) {
            uint32_t af[4][4], bf[4][2];
            #pragma unroll
            for (int mt = 0; mt < 4; mt++)
                ldsm4(af[mt], sA[cur] + (uint32_t)(((wrow * 64 + mt * 16 + fRow) * 40
                                                    + k16 * 16 + fColH) * 2));
            #pragma unroll
            for (int np = 0; np < 2; np++) {
                uint32_t t4[4];
                ldsm4(t4, sB[cur] + (uint32_t)(((wcol * 32 + np * 16 + fRow) * 40
                                                + k16 * 16 + fColH) * 2));
                bf[2*np][0] = t4[0]; bf[2*np][1] = t4[2];
                bf[2*np+1][0] = t4[1]; bf[2*np+1][1] = t4[3];
            }
            #pragma unroll
            for (int mt = 0; mt < 4; mt++)
                #pragma unroll
                for (int nt = 0; nt < 4; nt++)
                    mma_f16(c[mt][nt], af[mt], bf[nt][0], bf[nt][1]);
        }
        if (ks < 31) {
            #pragma unroll
            for (int i = 0; i < 4; i++) {
                int row = lrw + i * 32;
                int idx = row * 20 + (lc4 >> 1);
                *(uint2*)&Abuf[cur ^ 1][idx] = make_uint2(pack_f16(ra[i].x, ra[i].y),
                                                          pack_f16(ra[i].z, ra[i].w));
                *(uint2*)&Bbuf[cur ^ 1][idx] = make_uint2(pack_f16(rb[i].x, rb[i].y),
                                                          pack_f16(rb[i].z, rb[i].w));
            }
        }
        __syncthreads();
    }

    const int lrow = lane >> 2;
    const int lk   = lane & 3;
    #pragma unroll
    for (int mt = 0; mt < 4; mt++) {
        #pragma unroll
        for (int half = 0; half < 2; half++) {
            int row = bm + wrow * 64 + mt * 16 + lrow + half * 8;
            #pragma unroll
            for (int nt = 0; nt < 4; nt++) {
                int col = bn + wcol * 32 + nt * 8 + lk * 2;
                float v0 = c[mt][nt][half * 2];
                float v1 = c[mt][nt][half * 2 + 1];
                if (MODE == 0) {
                    int b = row >> 11, t = row & 2047;
                    int h = col >> 6, d = col & 63;
                    *(uint32_t*)&hdst[(((size_t)(b * Hc + h)) * Tc + t) * HDc + d] =
                        pack_f16((v0 + bias[col]) * scale, (v1 + bias[col + 1]) * scale);
                } else {
                    *(float2*)&Cout[(size_t)row * Ec + col] =
                        make_float2(v0 + bias[col], v1 + bias[col + 1]);
                }
            }
        }
    }
}

// ---------------------------------------------------------------------------
// attn_fused (all-fp16, single-buffered — R13 proven config): per (bh, 64-row
// t-tile). Flash online softmax. Writes only g_o and g_c.
// ---------------------------------------------------------------------------
__global__ void __launch_bounds__(128, 4) attn_fused(
    const unsigned char* __restrict__ am, const unsigned char* __restrict__ kpm)
{
    __shared__ uint32_t Ks[64 * 36];
    __shared__ uint32_t Vs[64 * 36];

    const int tid  = threadIdx.x;
    const int w    = tid >> 5;
    const int lane = tid & 31;
    const int lrow = lane >> 2;
    const int lk   = lane & 3;
    const int tbase = blockIdx.x * 64;
    const int bh = blockIdx.y;
    const int b = bh >> 4, h = bh & 15;

    const __half* Q  = g_q + (size_t)bh * Tc * HDc;
    const __half* Kg = g_k + (size_t)bh * Sc * HDc;
    const __half* Vg = g_v + (size_t)bh * Sc * HDc;

    const uint32_t sK = smem_u32(Ks);
    const uint32_t sV = smem_u32(Vs);

    const int fRow  = (lane & 7) + ((lane >> 3) & 1) * 8;
    const int fColH = (lane >> 4) * 8;

    #pragma unroll
    for (int i = 0; i < 4; i++) {
        int flat = tid + i * 128;
        int row = flat >> 3, c8 = (flat & 7) * 8;
        *(uint4*)((char*)Ks + row * 144 + c8 * 2) =
            *(const uint4*)(Q + (size_t)(tbase + row) * HDc + c8);
    }
    __syncthreads();
    uint32_t aQ[4][4];
    #pragma unroll
    for (int ks = 0; ks < 4; ks++)
        ldsm4(aQ[ks], sK + (uint32_t)((w * 16 + fRow) * 144 + (ks * 16 + fColH) * 2));
    __syncthreads();

    float Oa[8][4];
    #pragma unroll
    for (int i = 0; i < 8; i++)
        #pragma unroll
        for (int u = 0; u < 4; u++) Oa[i][u] = 0.f;
    float m_lo = -1e30f, m_hi = -1e30f, s_lo = 0.f, s_hi = 0.f;

    const int t_lo = tbase + w * 16 + lrow;
    const int t_hi = t_lo + 8;

    for (int s0 = 0; s0 < Sc; s0 += 64) {
        #pragma unroll
        for (int i = 0; i < 4; i++) {
            int flat = tid + i * 128;
            int row = flat >> 3, c8 = (flat & 7) * 8;
            *(uint4*)((char*)Ks + row * 144 + c8 * 2) =
                *(const uint4*)(Kg + (size_t)(s0 + row) * HDc + c8);
            *(uint4*)((char*)Vs + row * 144 + c8 * 2) =
                *(const uint4*)(Vg + (size_t)(s0 + row) * HDc + c8);
        }
        __syncthreads();

        float S[8][4];
        #pragma unroll
        for (int nt = 0; nt < 8; nt++)
            #pragma unroll
            for (int u = 0; u < 4; u++) S[nt][u] = 0.f;
        #pragma unroll
        for (int ks = 0; ks < 4; ks++) {
            #pragma unroll
            for (int np = 0; np < 4; np++) {
                uint32_t t4[4];
                ldsm4(t4, sK + (uint32_t)((np * 16 + fRow) * 144 + (ks * 16 + fColH) * 2));
                mma_f16(S[2*np],     aQ[ks], t4[0], t4[2]);
                mma_f16(S[2*np + 1], aQ[ks], t4[1], t4[3]);
            }
        }

        float tmax_lo = -1e30f, tmax_hi = -1e30f;
        #pragma unroll
        for (int nt = 0; nt < 8; nt++) {
            int col = s0 + nt * 8 + lk * 2;
            uchar2 a0 = *(const uchar2*)&am[(size_t)t_lo * Sc + col];
            uchar2 a1 = *(const uchar2*)&am[(size_t)t_hi * Sc + col];
            uchar2 kp = *(const uchar2*)&kpm[(size_t)b * Sc + col];
            if (a0.x | kp.x) S[nt][0] = 1e-10f;
            if (a0.y | kp.y) S[nt][1] = 1e-10f;
            if (a1.x | kp.x) S[nt][2] = 1e-10f;
            if (a1.y | kp.y) S[nt][3] = 1e-10f;
            tmax_lo = fmaxf(tmax_lo, fmaxf(S[nt][0], S[nt][1]));
            tmax_hi = fmaxf(tmax_hi, fmaxf(S[nt][2], S[nt][3]));
        }
        tmax_lo = fmaxf(tmax_lo, __shfl_xor_sync(0xffffffffu, tmax_lo, 1));
        tmax_lo = fmaxf(tmax_lo, __shfl_xor_sync(0xffffffffu, tmax_lo, 2));
        tmax_hi = fmaxf(tmax_hi, __shfl_xor_sync(0xffffffffu, tmax_hi, 1));
        tmax_hi = fmaxf(tmax_hi, __shfl_xor_sync(0xffffffffu, tmax_hi, 2));

        float mnew_lo = fmaxf(m_lo, tmax_lo);
        float mnew_hi = fmaxf(m_hi, tmax_hi);
        float f_lo = __expf(m_lo - mnew_lo);
        float f_hi = __expf(m_hi - mnew_hi);
        m_lo = mnew_lo; m_hi = mnew_hi;
        s_lo *= f_lo;   s_hi *= f_hi;
        #pragma unroll
        for (int nd = 0; nd < 8; nd++) {
            Oa[nd][0] *= f_lo; Oa[nd][1] *= f_lo;
            Oa[nd][2] *= f_hi; Oa[nd][3] *= f_hi;
        }

        uint32_t aP[4][4];
        #pragma unroll
        for (int nt = 0; nt < 8; nt++) {
            float p0 = __expf(S[nt][0] - m_lo);
            float p1 = __expf(S[nt][1] - m_lo);
            float p2 = __expf(S[nt][2] - m_hi);
            float p3 = __expf(S[nt][3] - m_hi);
            s_lo += p0 + p1;
            s_hi += p2 + p3;
            int kk = nt >> 1, hi = (nt & 1) * 2;
            aP[kk][hi]     = pack_f16(p0, p1);
            aP[kk][hi + 1] = pack_f16(p2, p3);
        }

        #pragma unroll
        for (int kk = 0; kk < 4; kk++) {
            int vrow = kk * 16 + fRow;
            #pragma unroll
            for (int nd16 = 0; nd16 < 4; nd16++) {
                uint32_t t4[4];
                int vcol = nd16 * 16 + (lane >> 4) * 8;
                ldsm4t(t4, sV + (uint32_t)(vrow * 144 + vcol * 2));
                mma_f16(Oa[nd16 * 2],     aP[kk], t4[0], t4[1]);
                mma_f16(Oa[nd16 * 2 + 1], aP[kk], t4[2], t4[3]);
            }
        }
        __syncthreads();
    }

    float r_lo = s_lo, r_hi = s_hi;
    r_lo += __shfl_xor_sync(0xffffffffu, r_lo, 1);
    r_lo += __shfl_xor_sync(0xffffffffu, r_lo, 2);
    r_hi += __shfl_xor_sync(0xffffffffu, r_hi, 1);
    r_hi += __shfl_xor_sync(0xffffffffu, r_hi, 2);
    const float inv_lo = 1.0f / r_lo;
    const float inv_hi = 1.0f / r_hi;

    #pragma unroll
    for (int nd = 0; nd < 8; nd++) {
        int d = nd * 8 + lk * 2;
        *(float2*)&g_o[(((size_t)b * Tc + t_lo) * Hc + h) * HDc + d] =
            make_float2(Oa[nd][0] * inv_lo, Oa[nd][1] * inv_lo);
        *(float2*)&g_o[(((size_t)b * Tc + t_hi) * Hc + h) * HDc + d] =
            make_float2(Oa[nd][2] * inv_hi, Oa[nd][3] * inv_hi);
    }
    if (lk == 0) {
        g_c[(size_t)bh * Tc + t_lo] = m_lo + __logf(r_lo);
        g_c[(size_t)bh * Tc + t_hi] = m_hi + __logf(r_hi);
    }
}

// ---------------------------------------------------------------------------
// headmax_gemm: per (b, 64x128 t x s tile), 256 threads / 8 warps (4t x 2s).
// Recomputes S_h (bit-identical fp16 mma) for all 16 heads;
//   attn_max[b,t,s] = exp(max_h (S_h - c[b,h,t])).
// Wider s-tile amortizes syncs and halves Q traffic vs 64x64.
// ---------------------------------------------------------------------------
__global__ void __launch_bounds__(256, 2) headmax_gemm(
    const unsigned char* __restrict__ am, const unsigned char* __restrict__ kpm,
    float* __restrict__ out2)
{
    __shared__ uint32_t Qs[64 * 36];     //  64 x 72-half
    __shared__ uint32_t Ks[128 * 36];    // 128 x 72-half

    const int tid  = threadIdx.x;
    const int w    = tid >> 5;
    const int lane = tid & 31;
    const int lrow = lane >> 2;
    const int lk   = lane & 3;
    const int wt = w & 3;                // t-group 0..3
    const int ws = w >> 2;               // s-half 0..1
    const int b  = blockIdx.z;
    const int tb = blockIdx.y * 64;
    const int sb = blockIdx.x * 128;

    const uint32_t sQ = smem_u32(Qs);
    const uint32_t sKb = smem_u32(Ks);

    const int fRow  = (lane & 7) + ((lane >> 3) & 1) * 8;
    const int fColH = (lane >> 4) * 8;

    const int ldRow = tid >> 3;          // 0..31
    const int ldC8  = (tid & 7) * 8;

    const int t_lo = tb + wt * 16 + lrow;
    const int t_hi = t_lo + 8;
    const int scol0 = sb + ws * 64;      // this warp's 64-col s-window

    // precompute per-thread mask bits (bit nt*4+u)
    uint32_t mbits = 0;
    #pragma unroll
    for (int nt = 0; nt < 8; nt++) {
        int col = scol0 + nt * 8 + lk * 2;
        uchar2 a0 = *(const uchar2*)&am[(size_t)t_lo * Sc + col];
        uchar2 a1 = *(const uchar2*)&am[(size_t)t_hi * Sc + col];
        uchar2 kp = *(const uchar2*)&kpm[(size_t)b * Sc + col];
        if (a0.x | kp.x) mbits |= 1u << (nt * 4 + 0);
        if (a0.y | kp.y) mbits |= 1u << (nt * 4 + 1);
        if (a1.x | kp.x) mbits |= 1u << (nt * 4 + 2);
        if (a1.y | kp.y) mbits |= 1u << (nt * 4 + 3);
    }

    float best[8][4];
    #pragma unroll
    for (int nt = 0; nt < 8; nt++)
        #pragma unroll
        for (int u = 0; u < 4; u++) best[nt][u] = -1e30f;

    for (int h = 0; h < Hc; h++) {
        const int bh = b * Hc + h;
        const __half* Q  = g_q + (size_t)bh * Tc * HDc;
        const __half* Kg = g_k + (size_t)bh * Sc * HDc;

        // stage Q (64 rows, 2 passes) and K (128 rows, 4 passes)
        #pragma unroll
        for (int i = 0; i < 2; i++) {
            int row = ldRow + i * 32;
            *(uint4*)((char*)Qs + row * 144 + ldC8 * 2) =
                *(const uint4*)(Q + (size_t)(tb + row) * HDc + ldC8);
        }
        #pragma unroll
        for (int i = 0; i < 4; i++) {
            int row = ldRow + i * 32;
            *(uint4*)((char*)Ks + row * 144 + ldC8 * 2) =
                *(const uint4*)(Kg + (size_t)(sb + row) * HDc + ldC8);
        }
        __syncthreads();

        uint32_t aQ[4][4];
        #pragma unroll
        for (int ks = 0; ks < 4; ks++)
            ldsm4(aQ[ks], sQ + (uint32_t)((wt * 16 + fRow) * 144 + (ks * 16 + fColH) * 2));

        float S[8][4];
        #pragma unroll
        for (int nt = 0; nt < 8; nt++)
            #pragma unroll
            for (int u = 0; u < 4; u++) S[nt][u] = 0.f;
        #pragma unroll
        for (int ks = 0; ks < 4; ks++) {
            #pragma unroll
            for (int np = 0; np < 4; np++) {
                uint32_t t4[4];
                ldsm4(t4, sKb + (uint32_t)((ws * 64 + np * 16 + fRow) * 144
                                           + (ks * 16 + fColH) * 2));
                mma_f16(S[2*np],     aQ[ks], t4[0], t4[2]);
                mma_f16(S[2*np + 1], aQ[ks], t4[1], t4[3]);
            }
        }

        const float c_lo = g_c[(size_t)bh * Tc + t_lo];
        const float c_hi = g_c[(size_t)bh * Tc + t_hi];
        #pragma unroll
        for (int nt = 0; nt < 8; nt++) {
            float v0 = (mbits >> (nt * 4 + 0)) & 1 ? 1e-10f : S[nt][0];
            float v1 = (mbits >> (nt * 4 + 1)) & 1 ? 1e-10f : S[nt][1];
            float v2 = (mbits >> (nt * 4 + 2)) & 1 ? 1e-10f : S[nt][2];
            float v3 = (mbits >> (nt * 4 + 3)) & 1 ? 1e-10f : S[nt][3];
            best[nt][0] = fmaxf(best[nt][0], v0 - c_lo);
            best[nt][1] = fmaxf(best[nt][1], v1 - c_lo);
            best[nt][2] = fmaxf(best[nt][2], v2 - c_hi);
            best[nt][3] = fmaxf(best[nt][3], v3 - c_hi);
        }
        __syncthreads();
    }

    #pragma unroll
    for (int nt = 0; nt < 8; nt++) {
        int col = scol0 + nt * 8 + lk * 2;
        *(float2*)&out2[((size_t)b * Tc + t_lo) * Sc + col] =
            make_float2(__expf(best[nt][0]), __expf(best[nt][1]));
        *(float2*)&out2[((size_t)b * Tc + t_hi) * Sc + col] =
            make_float2(__expf(best[nt][2]), __expf(best[nt][3]));
    }
}

// ---------------------------------------------------------------------------
extern "C" void kernel_launch(void* const* d_in, const int* in_sizes, int n_in,
                              void* d_out, int out_size)
{
    const float* query = (const float*)d_in[0];
    const float* key   = (const float*)d_in[1];
    const float* value = (const float*)d_in[2];
    const unsigned char* kpm = (const unsigned char*)d_in[3];
    const unsigned char* am  = (const unsigned char*)d_in[4];
    const float* Wq = (const float*)d_in[5];
    const float* bq = (const float*)d_in[6];
    const float* Wk = (const float*)d_in[7];
    const float* bk = (const float*)d_in[8];
    const float* Wv = (const float*)d_in[9];
    const float* bv = (const float*)d_in[10];
    const float* Wo = (const float*)d_in[11];
    const float* bo = (const float*)d_in[12];

    float* out      = (float*)d_out;
    float* attn_max = (float*)d_out + (size_t)Bc * Tc * Ec;

    float *po;
    cudaGetSymbolAddress((void**)&po, g_o);

    static cudaStream_t s2 = nullptr;
    static cudaEvent_t evFork = nullptr, evJoin = nullptr;
    if (s2 == nullptr) {
        cudaStreamCreateWithFlags(&s2, cudaStreamNonBlocking);
        cudaEventCreateWithFlags(&evFork, cudaEventDisableTiming);
        cudaEventCreateWithFlags(&evJoin, cudaEventDisableTiming);
    }

    const int GEMM_SMEM = 4 * 2560 * 4;   // 40960 B (fp16 double buffer)
    cudaFuncSetAttribute(gemm_db<0>, cudaFuncAttributeMaxDynamicSharedMemorySize, GEMM_SMEM);
    cudaFuncSetAttribute(gemm_db<3>, cudaFuncAttributeMaxDynamicSharedMemorySize, GEMM_SMEM);

    dim3 thr(256);

    // Batched Q/K/V projections -> fp16 (grid.z = 0,1,2)
    gemm_db<0><<<dim3(Ec / 128, (Bc * Tc) / 128, 3), thr, GEMM_SMEM>>>(
        query, key, value, Wq, Wk, Wv, bq, bk, bv, nullptr);

    // Fused score + online softmax + P@V  (writes g_o, g_c only)
    attn_fused<<<dim3(Tc / 64, Bc * Hc), dim3(128)>>>(am, kpm);

    // fork: attn_max recompute on side stream, out-projection on main stream
    cudaEventRecord(evFork, 0);
    cudaStreamWaitEvent(s2, evFork, 0);

    headmax_gemm<<<dim3(Sc / 128, Tc / 64, Bc), dim3(256), 0, s2>>>(am, kpm, attn_max);

    gemm_db<3><<<dim3(Ec / 128, (Bc * Tc) / 128, 1), thr, GEMM_SMEM>>>(
        po, nullptr, nullptr, Wo, nullptr, nullptr, bo, nullptr, nullptr, out);

    cudaEventRecord(evJoin, s2);
    cudaStreamWaitEvent(0, evJoin, 0);
}